// round 4
// baseline (speedup 1.0000x reference)
#include <cuda_runtime.h>
#include <cstdint>

// Focal CTC loss — 2 timesteps per barrier (redundant-neighbor scheme).
// grid = 2B. CTAs [0,B): alpha recursion, warps 0-6 compute, warp 7 owns the
// cp.async row ring. Per barrier interval each thread computes alpha_t for
// states s, s-1, s-2 redundantly (bitwise identical to neighbors' own values),
// then alpha_{t+1}[s] entirely in registers -> one __syncthreads / 2 steps.
// CTAs [B,2B): coalesced sum_t exp(lp) -> focal weights. Final scalar
// factorizes: mean(outer(w,loss)) = mean(loss)*mean(w); fused via atomic ctr.

#define CFIX  256
#define DEPTH 8
#define NEG2  (-1e30f)
#define LOG2E 1.4426950408889634f
#define LN2   0.6931471805599453f

__device__ float g_loss[1024];
__device__ float g_wsum[1024];
__device__ unsigned int g_ctr = 0;

__device__ __forceinline__ float ex2f(float x){ float y; asm("ex2.approx.ftz.f32 %0,%1;":"=f"(y):"f"(x)); return y; }
__device__ __forceinline__ float lg2f(float x){ float y; asm("lg2.approx.ftz.f32 %0,%1;":"=f"(y):"f"(x)); return y; }

// 3-way log2-sum-exp (max term folded to 1) + natural-log emission e
__device__ __forceinline__ float lse3e(float a, float b, float c, float e) {
    float hi = fmaxf(a, b), lo = fminf(a, b);
    float m  = fmaxf(hi, c), o1 = fminf(hi, c);
    float ss = 1.0f + ex2f(o1 - m) + ex2f(lo - m);
    return fmaf(e, LOG2E, m + lg2f(ss));
}

__device__ __forceinline__ void finalize(float* out, int B, int L, int nCTA)
{
    __threadfence();
    unsigned v = atomicAdd(&g_ctr, 1u);
    if (v == (unsigned)(nCTA - 1)) {
        g_ctr = 0;
        __threadfence();
        float ls = 0.0f, ws = 0.0f;
        for (int i = 0; i < B; i++) {
            ls += __ldcg(&g_loss[i]);
            ws += __ldcg(&g_wsum[i]);
        }
        out[0] = (ls / (float)B) * (ws / ((float)B * (float)L));
    }
}

__global__ __launch_bounds__(256, 1)
void focal_ctc_kernel(const float* __restrict__ lp,      // (T,B,C)
                      const int*   __restrict__ targets, // (B*L)
                      const int*   __restrict__ in_len,  // (B)
                      const int*   __restrict__ tg_len,  // (B)
                      float*       __restrict__ out,
                      int T, int B, int L)
{
    __shared__ float ring[DEPTH][CFIX];  // log_probs row ring (8 KB)
    __shared__ float abuf[2][264];       // alpha double buffer, 4-pad front
    __shared__ float sums[CFIX];
    __shared__ float lastv[2];
    __shared__ float redw[8];

    const int tid = threadIdx.x, w = tid >> 5, lane = tid & 31;
    const int bid = blockIdx.x;
    const size_t tstr = (size_t)B * CFIX;

    // ================= reduce CTAs: focal weights =================
    if (bid >= B) {
        const int b = bid - B;
        const float* p = lp + (size_t)b * CFIX + tid;
        float acc = 0.0f;
        int t = 0;
        for (; t + 8 <= T; t += 8) {
            float v[8];
            #pragma unroll
            for (int j = 0; j < 8; j++) v[j] = __ldcg(p + (size_t)(t + j) * tstr);
            #pragma unroll
            for (int j = 0; j < 8; j++) acc += ex2f(v[j] * LOG2E);
        }
        for (; t < T; t++) acc += ex2f(__ldcg(p + (size_t)t * tstr) * LOG2E);
        sums[tid] = acc;
        __syncthreads();
        float wgt = 0.0f;
        if (tid < L) {
            int   c  = targets[b * L + tid];
            float pr = sums[c] * (1.0f / (float)T);
            float om = 1.0f - pr;
            wgt = om * om;                       // GAMMA = 2
        }
        #pragma unroll
        for (int o = 16; o; o >>= 1) wgt += __shfl_down_sync(0xFFFFFFFFu, wgt, o);
        if (lane == 0) redw[w] = wgt;
        __syncthreads();
        if (tid == 0) {
            float ws = 0.0f;
            #pragma unroll
            for (int i = 0; i < 8; i++) ws += redw[i];
            g_wsum[b] = ws;
            finalize(out, B, L, 2 * B);
        }
        return;
    }

    // ================= recursion CTAs =================
    const int b   = bid;
    const int S   = 2 * L + 1;
    const int len = in_len[b], tl = tg_len[b];
    const bool w7 = (w == 7);
    const bool isState = (tid < S);
    const int  bL = b * L;

    // ext symbol channel for state k (k<0 or even -> blank 0)
    auto extf = [&](int k) -> int {
        return (k >= 1 && (k & 1)) ? targets[bL + (k >> 1)] : 0;
    };
    const int s = tid;
    const int ch0 = extf(s), ch1 = extf(s - 1), ch2 = extf(s - 2);
    const int e3  = extf(s - 3), e4 = extf(s - 4);
    const bool al0 = (s >= 2) && (ch0 != 0) && (ch0 != ch2);
    const bool al1 = (s >= 3) && (ch1 != 0) && (ch1 != e3);
    const bool al2 = (s >= 4) && (ch2 != 0) && (ch2 != e4);

    // front pads (indices 0..3) in both buffers
    if (tid < 4) { abuf[0][tid] = NEG2; abuf[1][tid] = NEG2; }

    const float* rowb = lp + (size_t)b * CFIX;

    // warp 7 prologue: rows 0..6 committed (1 group per row), completed 0..2
    if (w7) {
        #pragma unroll
        for (int r = 0; r < DEPTH - 1; r++) {
            if (r < T) {
                const float* s0 = rowb + (size_t)r * tstr + lane * 4;
                uint32_t d0 = (uint32_t)__cvta_generic_to_shared(&ring[r][lane * 4]);
                asm volatile("cp.async.ca.shared.global [%0], [%1], 16;" :: "r"(d0), "l"(s0) : "memory");
                asm volatile("cp.async.ca.shared.global [%0], [%1], 16;" :: "r"(d0 + 512), "l"(s0 + 128) : "memory");
            }
            asm volatile("cp.async.commit_group;" ::: "memory");
        }
        asm volatile("cp.async.wait_group 4;" ::: "memory");
    }
    __syncthreads();                       // row 0..2 + pads visible

    // ---- t = 0 ----
    float e0  = ring[0][ch0];
    float cur = (isState && s < 2) ? e0 * LOG2E : NEG2;
    abuf[0][4 + tid] = cur;
    if (len == 1) {
        if (s == 2 * tl)     lastv[0] = cur;
        if (s == 2 * tl - 1) lastv[1] = cur;
    }

    int rb = 0;      // buffer holding alpha_{t-1}
    int t  = 1;
    for (; t + 1 < T; t += 2) {
        __syncthreads();   // alpha_{t-1} visible; rows t, t+1 ready; old reads done
        if (w7) {
            #pragma unroll
            for (int k = 0; k < 2; k++) {
                const int r = t + 6 + k;
                if (r < T) {
                    const float* s0 = rowb + (size_t)r * tstr + lane * 4;
                    uint32_t d0 = (uint32_t)__cvta_generic_to_shared(&ring[r & (DEPTH - 1)][lane * 4]);
                    asm volatile("cp.async.ca.shared.global [%0], [%1], 16;" :: "r"(d0), "l"(s0) : "memory");
                    asm volatile("cp.async.ca.shared.global [%0], [%1], 16;" :: "r"(d0 + 512), "l"(s0 + 128) : "memory");
                }
                asm volatile("cp.async.commit_group;" ::: "memory");
            }
            asm volatile("cp.async.wait_group 4;" ::: "memory");
        } else {
            const float* pr = abuf[rb];
            const int rt = t & (DEPTH - 1), rn = (t + 1) & (DEPTH - 1);
            float am1 = pr[3 + tid];        // alpha_{t-1}[s-1]
            float am2 = pr[2 + tid];        // [s-2]
            float am3 = pr[1 + tid];        // [s-3]
            float am4 = pr[0 + tid];        // [s-4]
            float e0t = ring[rt][ch0], e1t = ring[rt][ch1], e2t = ring[rt][ch2];
            float e0n = ring[rn][ch0];
            // step t: own state + two redundant neighbors (bitwise == theirs)
            float v0 = lse3e(cur, am1, al0 ? am2 : NEG2, e0t);
            float v1 = lse3e(am1, am2, al1 ? am3 : NEG2, e1t);
            float v2 = lse3e(am2, am3, al2 ? am4 : NEG2, e2t);
            // step t+1: pure register inputs
            float nv = lse3e(v0, v1, al0 ? v2 : NEG2, e0n);
            if (!isState) nv = NEG2;
            abuf[rb ^ 1][4 + tid] = nv;
            cur = nv;
            if (t == len - 1) {
                if (s == 2 * tl)     lastv[0] = v0;
                if (s == 2 * tl - 1) lastv[1] = v0;
            }
            if (t + 1 == len - 1) {
                if (s == 2 * tl)     lastv[0] = nv;
                if (s == 2 * tl - 1) lastv[1] = nv;
            }
        }
        rb ^= 1;
    }
    // leftover single step (T even -> t = T-1 here)
    if (t < T) {
        __syncthreads();
        if (!w7) {
            const float* pr = abuf[rb];
            float a1 = pr[3 + tid];
            float a2 = al0 ? pr[2 + tid] : NEG2;
            float e  = ring[t & (DEPTH - 1)][ch0];
            float nv = lse3e(cur, a1, a2, e);
            if (t == len - 1) {
                if (s == 2 * tl)     lastv[0] = nv;
                if (s == 2 * tl - 1) lastv[1] = nv;
            }
        }
    }
    if (w7) { asm volatile("cp.async.wait_group 0;" ::: "memory"); }
    __syncthreads();

    if (tid == 0) {
        float la = lastv[0], lb = lastv[1];
        float m  = fmaxf(la, lb);
        float ll = (m + lg2f(ex2f(la - m) + ex2f(lb - m))) * LN2;
        g_loss[b] = (ll > -5e29f) ? -ll : 0.0f;   // zero_infinity
        finalize(out, B, L, 2 * B);
    }
}

extern "C" void kernel_launch(void* const* d_in, const int* in_sizes, int n_in,
                              void* d_out, int out_size)
{
    const float* lp      = (const float*)d_in[0];
    const int*   targets = (const int*)d_in[1];
    const int*   in_len  = (const int*)d_in[2];
    const int*   tg_len  = (const int*)d_in[3];

    int B = in_sizes[2];                 // 64
    int L = in_sizes[1] / B;             // 100
    int T = in_sizes[0] / (B * CFIX);    // 1000

    focal_ctc_kernel<<<2 * B, 256>>>(lp, targets, in_len, tg_len, (float*)d_out, T, B, L);
}

// round 5
// speedup vs baseline: 1.0195x; 1.0195x over previous
#include <cuda_runtime.h>
#include <cstdint>

// Focal CTC loss — paired-state scan (2 states/thread, 1 compute warp/SMSP).
// grid = 2B. CTAs [0,B): warps 0-3 hold states (u=2i, v=2i+1) in registers;
// the recursion needs exactly ONE neighbor value per step (alpha[2i-1]),
// exchanged via a 128-float smem buffer. Warp 4 owns the cp.async row ring.
// Warps 5-7 idle-spin on the barrier (block stays 256 for the reduce CTAs).
// CTAs [B,2B): coalesced sum_t exp(lp) -> focal weights. Final scalar
// factorizes: mean(outer(w,loss)) = mean(loss)*mean(w); fused via atomic ctr.

#define CFIX  256
#define DEPTH 8
#define NEG2  (-1e30f)
#define LOG2E 1.4426950408889634f
#define LN2   0.6931471805599453f

__device__ float g_loss[1024];
__device__ float g_wsum[1024];
__device__ unsigned int g_ctr = 0;

__device__ __forceinline__ float ex2f(float x){ float y; asm("ex2.approx.ftz.f32 %0,%1;":"=f"(y):"f"(x)); return y; }
__device__ __forceinline__ float lg2f(float x){ float y; asm("lg2.approx.ftz.f32 %0,%1;":"=f"(y):"f"(x)); return y; }

__device__ __forceinline__ void finalize(float* out, int B, int L, int nCTA)
{
    __threadfence();
    unsigned v = atomicAdd(&g_ctr, 1u);
    if (v == (unsigned)(nCTA - 1)) {
        g_ctr = 0;
        __threadfence();
        float ls = 0.0f, ws = 0.0f;
        for (int i = 0; i < B; i++) {
            ls += __ldcg(&g_loss[i]);
            ws += __ldcg(&g_wsum[i]);
        }
        out[0] = (ls / (float)B) * (ws / ((float)B * (float)L));
    }
}

__global__ __launch_bounds__(256, 1)
void focal_ctc_kernel(const float* __restrict__ lp,      // (T,B,C)
                      const int*   __restrict__ targets, // (B*L)
                      const int*   __restrict__ in_len,  // (B)
                      const int*   __restrict__ tg_len,  // (B)
                      float*       __restrict__ out,
                      int T, int B, int L)
{
    __shared__ float ring[DEPTH][CFIX];  // log_probs row ring (8 KB)
    __shared__ float obuf[2][132];       // odd-state alphas, 1-pad front
    __shared__ float sums[CFIX];
    __shared__ float lastv[2];
    __shared__ float redw[8];

    const int tid = threadIdx.x, w = tid >> 5, lane = tid & 31;
    const int bid = blockIdx.x;
    const size_t tstr = (size_t)B * CFIX;

    // ================= reduce CTAs: focal weights =================
    if (bid >= B) {
        const int b = bid - B;
        const float* p = lp + (size_t)b * CFIX + tid;
        float acc = 0.0f;
        int t = 0;
        for (; t + 8 <= T; t += 8) {
            float v[8];
            #pragma unroll
            for (int j = 0; j < 8; j++) v[j] = __ldcg(p + (size_t)(t + j) * tstr);
            #pragma unroll
            for (int j = 0; j < 8; j++) acc += ex2f(v[j] * LOG2E);
        }
        for (; t < T; t++) acc += ex2f(__ldcg(p + (size_t)t * tstr) * LOG2E);
        sums[tid] = acc;
        __syncthreads();
        float wgt = 0.0f;
        if (tid < L) {
            int   c  = targets[b * L + tid];
            float pr = sums[c] * (1.0f / (float)T);
            float om = 1.0f - pr;
            wgt = om * om;                       // GAMMA = 2
        }
        #pragma unroll
        for (int o = 16; o; o >>= 1) wgt += __shfl_down_sync(0xFFFFFFFFu, wgt, o);
        if (lane == 0) redw[w] = wgt;
        __syncthreads();
        if (tid == 0) {
            float ws = 0.0f;
            #pragma unroll
            for (int i = 0; i < 8; i++) ws += redw[i];
            g_wsum[b] = ws;
            finalize(out, B, L, 2 * B);
        }
        return;
    }

    // ================= recursion CTAs =================
    const int b   = bid;
    const int S   = 2 * L + 1;
    const int len = in_len[b], tl = tg_len[b];
    const bool cw = (w < 4);             // compute warps: thread i = tid, states 2i, 2i+1
    const bool rw = (w == 4);            // ring warp
    const int  i  = tid;                 // pair index (valid for cw)
    const int  u  = 2 * i, v = 2 * i + 1;
    const bool isU = cw && (u < S), isV = cw && (v < S);

    int chV = 0; bool al = false;
    if (isV) {
        chV = targets[b * L + i];                 // symbol of state v=2i+1
        if (i >= 1) {
            int prevc = targets[b * L + i - 1];   // symbol of state v-2
            al = (chV != prevc);                  // chV != 0 always (targets >= 1)
        }
    }
    const bool capU = cw && (u == 2 * tl);        // state 2*tl (even)
    const bool capV = cw && (v == 2 * tl - 1);    // state 2*tl-1 (odd)

    if (tid == 0) { obuf[0][0] = NEG2; obuf[1][0] = NEG2; }

    const float* rowb = lp + (size_t)b * CFIX;

    // ring prologue: rows 0..6 committed (1 group/row), wait -> rows 0..2 done
    if (rw) {
        #pragma unroll
        for (int r = 0; r < DEPTH - 1; r++) {
            if (r < T) {
                const float* s0 = rowb + (size_t)r * tstr + lane * 4;
                uint32_t d0 = (uint32_t)__cvta_generic_to_shared(&ring[r][lane * 4]);
                asm volatile("cp.async.ca.shared.global [%0], [%1], 16;" :: "r"(d0), "l"(s0) : "memory");
                asm volatile("cp.async.ca.shared.global [%0], [%1], 16;" :: "r"(d0 + 512), "l"(s0 + 128) : "memory");
            }
            asm volatile("cp.async.commit_group;" ::: "memory");
        }
        asm volatile("cp.async.wait_group 4;" ::: "memory");
    }
    __syncthreads();                       // row 0 + pads visible

    // ---- t = 0 ----  (alpha0: state0 = e_blank, state1 = e_v; rest NEG)
    float aU = NEG2, aV = NEG2;
    if (cw) {
        if (i == 0) {
            aU = ring[0][0]   * LOG2E;
            aV = ring[0][chV] * LOG2E;
        }
        obuf[0][i + 1] = aV;
        if (len == 1) {
            if (capU) lastv[0] = aU;
            if (capV) lastv[1] = aV;
        }
    }

    for (int t = 1; t < T; t++) {
        __syncthreads();   // obuf(t-1) visible; ring row t ready; row t-2 reads done
        if (rw) {
            const int r = t + DEPTH - 2;
            if (r < T) {
                const float* s0 = rowb + (size_t)r * tstr + lane * 4;
                uint32_t d0 = (uint32_t)__cvta_generic_to_shared(&ring[r & (DEPTH - 1)][lane * 4]);
                asm volatile("cp.async.ca.shared.global [%0], [%1], 16;" :: "r"(d0), "l"(s0) : "memory");
                asm volatile("cp.async.ca.shared.global [%0], [%1], 16;" :: "r"(d0 + 512), "l"(s0 + 128) : "memory");
            }
            asm volatile("cp.async.commit_group;" ::: "memory");
            asm volatile("cp.async.wait_group 4;" ::: "memory");
        } else if (cw) {
            const int rt = t & (DEPTH - 1);
            float aVm1 = obuf[(t - 1) & 1][i];    // alpha_{t-1}[2i-1]
            float eB   = ring[rt][0];             // blank emission (broadcast)
            float eV   = ring[rt][chV];
            // newU = LSE2(aU, aVm1) + eB   (even state: no skip)
            float hiU = fmaxf(aU, aVm1), loU = fminf(aU, aVm1);
            float ssU = 1.0f + ex2f(loU - hiU);
            float nU  = fmaf(eB, LOG2E, hiU + lg2f(ssU));
            // newV = LSE3(aV, aU, al ? aVm1 : NEG) + eV   (v-1 = u is own reg)
            float a2  = al ? aVm1 : NEG2;
            float hi  = fmaxf(aV, aU), lo = fminf(aV, aU);
            float m   = fmaxf(hi, a2), o1 = fminf(hi, a2);
            float ss  = 1.0f + ex2f(o1 - m) + ex2f(lo - m);
            float nV  = fmaf(eV, LOG2E, m + lg2f(ss));
            aU = isU ? nU : NEG2;
            aV = isV ? nV : NEG2;
            obuf[t & 1][i + 1] = aV;
            if (t == len - 1) {
                if (capU) lastv[0] = aU;
                if (capV) lastv[1] = aV;
            }
        }
        // warps 5-7: fall through to barrier
    }
    if (rw) { asm volatile("cp.async.wait_group 0;" ::: "memory"); }
    __syncthreads();

    if (tid == 0) {
        float la = lastv[0], lb = lastv[1];
        float m  = fmaxf(la, lb);
        float ll = (m + lg2f(ex2f(la - m) + ex2f(lb - m))) * LN2;
        g_loss[b] = (ll > -5e29f) ? -ll : 0.0f;   // zero_infinity
        finalize(out, B, L, 2 * B);
    }
}

extern "C" void kernel_launch(void* const* d_in, const int* in_sizes, int n_in,
                              void* d_out, int out_size)
{
    const float* lp      = (const float*)d_in[0];
    const int*   targets = (const int*)d_in[1];
    const int*   in_len  = (const int*)d_in[2];
    const int*   tg_len  = (const int*)d_in[3];

    int B = in_sizes[2];                 // 64
    int L = in_sizes[1] / B;             // 100
    int T = in_sizes[0] / (B * CFIX);    // 1000

    focal_ctc_kernel<<<2 * B, 256>>>(lp, targets, in_len, tg_len, (float*)d_out, T, B, L);
}